// round 1
// baseline (speedup 1.0000x reference)
#include <cuda_runtime.h>
#include <math.h>

// Problem constants
#define Bz 32
#define Dd 128
#define Tt 2048
#define Kk 2048
#define Nn 65536   // Bz*Tt

// Output layout (concatenated reference tuple, all float32)
#define OFF_ZVQ     0
#define OFF_LOSS    8388608
#define OFF_EMBNEW  8388609
#define OFF_EMBSUM  8650753
#define OFF_ELEM    8912897
#define OFF_ENT     8914945
#define OFF_DK      8914946

// EMA constants (match reference fp32 rounding: (float)(1.0 - 0.99))
__device__ __constant__ float MUf  = 0.99f;
__device__ __constant__ float C1f  = (float)(1.0 - 0.99);

// Scratch (device globals; no allocation allowed)
__device__ int    g_idx[Nn];
__device__ int    g_cnt[Kk];
__device__ float  g_en2[Kk];
__device__ double g_loss;
__device__ double g_dk2;

// ---------------------------------------------------------------------------
// K0a: ||e_k||^2 per code. One warp per code, float4 loads.
// ---------------------------------------------------------------------------
__global__ void k_en2(const float* __restrict__ emb) {
    int k = blockIdx.x;
    int lane = threadIdx.x;  // 32
    float4 v = reinterpret_cast<const float4*>(emb + (size_t)k * Dd)[lane];
    float s = v.x * v.x + v.y * v.y + v.z * v.z + v.w * v.w;
    #pragma unroll
    for (int o = 16; o > 0; o >>= 1) s += __shfl_down_sync(0xffffffffu, s, o);
    if (lane == 0) g_en2[k] = s;
}

// ---------------------------------------------------------------------------
// K0b: init output emb_sum region to MU*emb_sum, zero counts + scalar accums.
// ---------------------------------------------------------------------------
__global__ void k_init(const float* __restrict__ emb_sum, float* __restrict__ out_sum) {
    int i = blockIdx.x * 256 + threadIdx.x;
    if (i < Kk * Dd) out_sum[i] = __fmul_rn(MUf, emb_sum[i]);
    if (i < Kk) g_cnt[i] = 0;
    if (i == 0) { g_loss = 0.0; g_dk2 = 0.0; }
}

// ---------------------------------------------------------------------------
// K1: fused GEMM-argmin. Block: 64 rows (t) x all K (chunks of 128 codes).
// 512 threads, frag 2 rows x 8 cols per thread.
// zs[d][t] stride 64 (natural transpose: t contiguous in gmem).
// es[d][c] stride 132 (transposed at load, lane-varies-c => STS conflict-free,
//                      b-frag LDS.128 is a per-warp broadcast).
// ---------------------------------------------------------------------------
#define AT 512
__global__ __launch_bounds__(AT, 1)
void k_assign(const float* __restrict__ z, const float* __restrict__ emb)
{
    extern __shared__ float sm[];
    float* zs = sm;              // [128][64]
    float* es = sm + 128 * 64;   // [128][132]

    const int tid = threadIdx.x;
    const int n0  = blockIdx.x * 64;
    const int b   = n0 >> 11;     // / Tt
    const int t0  = n0 & 2047;

    // Load z tile transposed-for-free: zs[d][t_local]
    {
        const float* zb = z + (size_t)b * (Dd * Tt) + t0;
        for (int i = tid; i < 128 * 16; i += AT) {        // 2048 float4s
            int d  = i >> 4;
            int t4 = (i & 15) << 2;
            float4 v = *reinterpret_cast<const float4*>(zb + d * Tt + t4);
            *reinterpret_cast<float4*>(zs + d * 64 + t4) = v;
        }
    }

    const int rg = tid & 31;   // rows 2*rg, 2*rg+1
    const int cg = tid >> 5;   // cols 8*cg .. 8*cg+7  (cg constant per warp)

    float bestv0 = 3.4e38f, bestv1 = 3.4e38f;
    int   bestk0 = 0,       bestk1 = 0;

    for (int kc = 0; kc < Kk; kc += 128) {
        __syncthreads();
        // Load 128 codes transposed: es[d][c]. Lanes vary c (conflict-free STS).
        for (int i = tid; i < 128 * 32; i += AT) {
            int c  = i & 127;
            int d4 = i >> 7;
            float4 v = *reinterpret_cast<const float4*>(emb + (size_t)(kc + c) * Dd + (d4 << 2));
            es[(d4 * 4 + 0) * 132 + c] = v.x;
            es[(d4 * 4 + 1) * 132 + c] = v.y;
            es[(d4 * 4 + 2) * 132 + c] = v.z;
            es[(d4 * 4 + 3) * 132 + c] = v.w;
        }
        __syncthreads();

        float acc0[8], acc1[8];
        #pragma unroll
        for (int j = 0; j < 8; j++) { acc0[j] = 0.f; acc1[j] = 0.f; }

        #pragma unroll 4
        for (int d = 0; d < 128; d++) {
            float2 a  = *reinterpret_cast<const float2*>(zs + d * 64 + 2 * rg);
            float4 u  = *reinterpret_cast<const float4*>(es + d * 132 + 8 * cg);
            float4 w  = *reinterpret_cast<const float4*>(es + d * 132 + 8 * cg + 4);
            float bb[8] = {u.x, u.y, u.z, u.w, w.x, w.y, w.z, w.w};
            #pragma unroll
            for (int j = 0; j < 8; j++) {
                acc0[j] += a.x * bb[j];
                acc1[j] += a.y * bb[j];
            }
        }

        #pragma unroll
        for (int j = 0; j < 8; j++) {
            int k = kc + 8 * cg + j;
            float en = g_en2[k];
            float s0 = en - 2.f * acc0[j];
            float s1 = en - 2.f * acc1[j];
            if (s0 < bestv0) { bestv0 = s0; bestk0 = k; }
            if (s1 < bestv1) { bestv1 = s1; bestk1 = k; }
        }
    }

    // Cross-cg reduction (first-min tie-break preserved by ascending k order)
    __syncthreads();
    float* rv = sm;                         // [64][16]
    int*   ri = (int*)(sm + 64 * 16);       // [64][16]
    rv[(2 * rg + 0) * 16 + cg] = bestv0;
    rv[(2 * rg + 1) * 16 + cg] = bestv1;
    ri[(2 * rg + 0) * 16 + cg] = bestk0;
    ri[(2 * rg + 1) * 16 + cg] = bestk1;
    __syncthreads();
    if (tid < 64) {
        float bv = rv[tid * 16];
        int   bk = ri[tid * 16];
        #pragma unroll
        for (int c = 1; c < 16; c++) {
            float v  = rv[tid * 16 + c];
            int   k2 = ri[tid * 16 + c];
            if (v < bv || (v == bv && k2 < bk)) { bv = v; bk = k2; }
        }
        g_idx[n0 + tid] = bk;
    }
}

// ---------------------------------------------------------------------------
// K2a: histogram counts
// ---------------------------------------------------------------------------
__global__ void k_count() {
    int n = blockIdx.x * 256 + threadIdx.x;
    atomicAdd(&g_cnt[g_idx[n]], 1);
}

// ---------------------------------------------------------------------------
// K2b: scatter-add (1-MU)*z into pre-initialized emb_sum_n output region.
// Linear over (b,d,t); coalesced z and idx reads.
// ---------------------------------------------------------------------------
__global__ void k_scatter(const float* __restrict__ z, float* __restrict__ out_sum) {
    int i = blockIdx.x * 256 + threadIdx.x;      // over Bz*Dd*Tt
    int t = i & 2047;
    int d = (i >> 11) & 127;
    int b = i >> 18;
    int k = g_idx[(b << 11) + t];
    atomicAdd(&out_sum[k * Dd + d], __fmul_rn(C1f, z[i]));
}

// ---------------------------------------------------------------------------
// K3: z_vq_out gather + z_enc_loss (double accumulate).
// Block: (32 t) x (128 d looped by ty). Codebook rows staged in SMEM.
// ---------------------------------------------------------------------------
__global__ void k_output(const float* __restrict__ z, const float* __restrict__ emb,
                         float* __restrict__ out_zvq) {
    __shared__ int    kk[32];
    __shared__ float  er[32 * 133];   // stride 133 -> conflict-free [tx][d] reads
    __shared__ double red[256];
    int tx  = threadIdx.x;            // 32
    int ty  = threadIdx.y;            // 8
    int tid = ty * 32 + tx;
    int t0  = blockIdx.x * 32;
    int b   = blockIdx.y;

    if (tid < 32) kk[tid] = g_idx[b * Tt + t0 + tid];
    __syncthreads();
    // Stage the 32 codebook rows (coalesced along d)
    for (int i = tid; i < 32 * 32; i += 256) {
        int r  = i >> 5;
        int d4 = (i & 31) << 2;
        float4 v = *reinterpret_cast<const float4*>(emb + (size_t)kk[r] * Dd + d4);
        er[r * 133 + d4 + 0] = v.x;
        er[r * 133 + d4 + 1] = v.y;
        er[r * 133 + d4 + 2] = v.z;
        er[r * 133 + d4 + 3] = v.w;
    }
    __syncthreads();

    double loc = 0.0;
    size_t base = (size_t)b * Dd * Tt + t0 + tx;
    for (int d = ty; d < Dd; d += 8) {
        float v  = er[tx * 133 + d];
        float zv = z[base + (size_t)d * Tt];
        out_zvq[base + (size_t)d * Tt] = v;
        float df = v - zv;
        loc += (double)df * (double)df;
    }
    red[tid] = loc;
    __syncthreads();
    for (int s = 128; s > 0; s >>= 1) {
        if (tid < s) red[tid] += red[tid + s];
        __syncthreads();
    }
    if (tid == 0) atomicAdd(&g_loss, red[0]);
}

// ---------------------------------------------------------------------------
// K4: emb_new, emb_elem_n, dk partials
// ---------------------------------------------------------------------------
__global__ void k_new(const float* __restrict__ emb, const float* __restrict__ emb_elem,
                      const float* __restrict__ emb_rand,
                      const float* __restrict__ out_sum,
                      float* __restrict__ out_new, float* __restrict__ out_elem) {
    __shared__ double red[256];
    int i = blockIdx.x * 256 + threadIdx.x;  // Kk*Dd
    int k = i >> 7;
    int d = i & 127;
    // Match reference fp32 rounding exactly: mul, mul, add (no FMA)
    float ee = __fadd_rn(__fmul_rn(MUf, emb_elem[k]), __fmul_rn(C1f, (float)g_cnt[k]));
    float v  = (ee >= 1.0f) ? (out_sum[i] / ee) : emb_rand[i];
    out_new[i] = v;
    if (d == 0) out_elem[k] = ee;
    float df = v - emb[i];
    red[threadIdx.x] = (double)df * (double)df;
    __syncthreads();
    for (int s = 128; s > 0; s >>= 1) {
        if (threadIdx.x < s) red[threadIdx.x] += red[threadIdx.x + s];
        __syncthreads();
    }
    if (threadIdx.x == 0) atomicAdd(&g_dk2, red[0]);
}

// ---------------------------------------------------------------------------
// K5: entropy + scalar outputs
// ---------------------------------------------------------------------------
__global__ void k_final(float* __restrict__ out) {
    __shared__ double red[256];
    int tid = threadIdx.x;
    double s = 0.0;
    for (int k = tid; k < Kk; k += 256) {
        float p = (float)g_cnt[k] * (1.0f / 65536.0f);
        s += (double)(p * logf(p + 1e-8f));
    }
    red[tid] = s;
    __syncthreads();
    for (int st = 128; st > 0; st >>= 1) {
        if (tid < st) red[tid] += red[tid + st];
        __syncthreads();
    }
    if (tid == 0) {
        out[OFF_LOSS] = (float)g_loss;
        out[OFF_ENT]  = expf(-(float)red[0]);
        out[OFF_DK]   = (float)(sqrt(g_dk2) / 512.0);
    }
}

// ---------------------------------------------------------------------------
extern "C" void kernel_launch(void* const* d_in, const int* in_sizes, int n_in,
                              void* d_out, int out_size) {
    const float* z        = (const float*)d_in[0];
    const float* emb      = (const float*)d_in[1];
    const float* emb_sum  = (const float*)d_in[2];
    const float* emb_elem = (const float*)d_in[3];
    const float* emb_rand = (const float*)d_in[4];
    float* out      = (float*)d_out;
    float* out_zvq  = out + OFF_ZVQ;
    float* out_new  = out + OFF_EMBNEW;
    float* out_sum  = out + OFF_EMBSUM;
    float* out_elem = out + OFF_ELEM;

    const int assign_smem = (128 * 64 + 128 * 132) * (int)sizeof(float);  // 100352 B
    cudaFuncSetAttribute(k_assign, cudaFuncAttributeMaxDynamicSharedMemorySize, assign_smem);

    k_en2<<<Kk, 32>>>(emb);
    k_init<<<(Kk * Dd + 255) / 256, 256>>>(emb_sum, out_sum);
    k_assign<<<Nn / 64, AT, assign_smem>>>(z, emb);
    k_count<<<Nn / 256, 256>>>();
    k_scatter<<<(Bz * Dd * Tt) / 256, 256>>>(z, out_sum);
    k_output<<<dim3(Tt / 32, Bz), dim3(32, 8)>>>(z, emb, out_zvq);
    k_new<<<(Kk * Dd) / 256, 256>>>(emb, emb_elem, emb_rand, out_sum, out_new, out_elem);
    k_final<<<1, 256>>>(out);
}

// round 2
// speedup vs baseline: 1.3721x; 1.3721x over previous
#include <cuda_runtime.h>
#include <math.h>

// Problem constants
#define Bz 32
#define Dd 128
#define Tt 2048
#define Kk 2048
#define Nn 65536   // Bz*Tt

// Output layout (concatenated reference tuple, all float32)
#define OFF_ZVQ     0
#define OFF_LOSS    8388608
#define OFF_EMBNEW  8388609
#define OFF_EMBSUM  8650753
#define OFF_ELEM    8912897
#define OFF_ENT     8914945
#define OFF_DK      8914946

__device__ __constant__ float MUf  = 0.99f;
__device__ __constant__ float C1f  = (float)(1.0 - 0.99);

// Scratch (device globals; no allocation allowed)
__device__ int    g_idx[Nn];
__device__ int    g_cnt[Kk];
__device__ float  g_en2[Kk];
__device__ double g_loss;
__device__ double g_dk2;

// ---------------------------------------------------------------------------
// Packed f32x2 helpers (Blackwell FFMA2 — ptxas never auto-fuses this)
// ---------------------------------------------------------------------------
__device__ __forceinline__ unsigned long long ffma2(unsigned long long a,
                                                    unsigned long long b,
                                                    unsigned long long c) {
    unsigned long long d;
    asm("fma.rn.f32x2 %0, %1, %2, %3;" : "=l"(d) : "l"(a), "l"(b), "l"(c));
    return d;
}
__device__ __forceinline__ unsigned long long splat2(float x) {
    unsigned long long d;
    asm("mov.b64 %0, {%1, %1};" : "=l"(d) : "r"(__float_as_uint(x)));
    return d;
}
__device__ __forceinline__ float2 unpack2(unsigned long long v) {
    float2 r;
    asm("mov.b64 {%0, %1}, %2;" : "=f"(r.x), "=f"(r.y) : "l"(v));
    return r;
}

// ---------------------------------------------------------------------------
// K0a: ||e_k||^2 per code. One warp per code, float4 loads.
// ---------------------------------------------------------------------------
__global__ void k_en2(const float* __restrict__ emb) {
    int k = blockIdx.x;
    int lane = threadIdx.x;  // 32
    float4 v = reinterpret_cast<const float4*>(emb + (size_t)k * Dd)[lane];
    float s = v.x * v.x + v.y * v.y + v.z * v.z + v.w * v.w;
    #pragma unroll
    for (int o = 16; o > 0; o >>= 1) s += __shfl_down_sync(0xffffffffu, s, o);
    if (lane == 0) g_en2[k] = s;
}

// ---------------------------------------------------------------------------
// K0b: init output emb_sum region to MU*emb_sum, zero counts + scalar accums.
// ---------------------------------------------------------------------------
__global__ void k_init(const float* __restrict__ emb_sum, float* __restrict__ out_sum) {
    int i = blockIdx.x * 256 + threadIdx.x;
    if (i < Kk * Dd) out_sum[i] = __fmul_rn(MUf, emb_sum[i]);
    if (i < Kk) g_cnt[i] = 0;
    if (i == 0) { g_loss = 0.0; g_dk2 = 0.0; }
}

// ---------------------------------------------------------------------------
// K1: fused GEMM-argmin with packed FFMA2.
// Block: 128 rows (t) x K chunks of 128 codes. 512 threads.
// Frag: 4 rows x 8 cols per thread; accumulators are f32x2 pairs over
// adjacent COLUMNS so b-operands come packed straight from LDS.128.
// zs[d][t] stride 128 (t contiguous in gmem -> free transpose).
// es[d][c] stride 132 (transposed at load; b-reads are warp broadcasts).
// ---------------------------------------------------------------------------
#define AT 512
__global__ __launch_bounds__(AT, 1)
void k_assign(const float* __restrict__ z, const float* __restrict__ emb)
{
    extern __shared__ float sm[];
    float* zs = sm;               // [128][128]
    float* es = sm + 128 * 128;   // [128][132]

    const int tid = threadIdx.x;
    const int n0  = blockIdx.x * 128;
    const int b   = n0 >> 11;     // / Tt
    const int t0  = n0 & 2047;

    // Load z tile transposed-for-free: zs[d][t_local]
    {
        const float* zb = z + (size_t)b * (Dd * Tt) + t0;
        #pragma unroll
        for (int it = 0; it < 8; it++) {          // 128*32 float4s / 512 thr
            int i  = it * AT + tid;
            int d  = i >> 5;
            int t4 = (i & 31) << 2;
            float4 v = *reinterpret_cast<const float4*>(zb + d * Tt + t4);
            *reinterpret_cast<float4*>(zs + d * 128 + t4) = v;
        }
    }

    const int rg = tid & 31;   // rows 4*rg .. 4*rg+3
    const int cg = tid >> 5;   // cols 8*cg .. 8*cg+7  (constant per warp)

    float bestv[4];
    int   bestk[4];
    #pragma unroll
    for (int r = 0; r < 4; r++) { bestv[r] = 3.4e38f; bestk[r] = 0; }

    for (int kc = 0; kc < Kk; kc += 128) {
        __syncthreads();
        // Load 128 codes transposed: es[d][c]. Lanes vary c (conflict-free STS).
        #pragma unroll
        for (int it = 0; it < 8; it++) {
            int i  = it * AT + tid;
            int c  = i & 127;
            int d4 = i >> 7;
            float4 v = *reinterpret_cast<const float4*>(emb + (size_t)(kc + c) * Dd + (d4 << 2));
            es[(d4 * 4 + 0) * 132 + c] = v.x;
            es[(d4 * 4 + 1) * 132 + c] = v.y;
            es[(d4 * 4 + 2) * 132 + c] = v.z;
            es[(d4 * 4 + 3) * 132 + c] = v.w;
        }
        __syncthreads();

        unsigned long long acc[4][4];   // [row][colpair], each = 2 adjacent cols
        #pragma unroll
        for (int r = 0; r < 4; r++)
            #pragma unroll
            for (int p = 0; p < 4; p++) acc[r][p] = 0ULL;

        #pragma unroll 8
        for (int d = 0; d < 128; d++) {
            float4 a = *reinterpret_cast<const float4*>(zs + d * 128 + 4 * rg);
            ulonglong2 b0 = *reinterpret_cast<const ulonglong2*>(es + d * 132 + 8 * cg);
            ulonglong2 b1 = *reinterpret_cast<const ulonglong2*>(es + d * 132 + 8 * cg + 4);
            unsigned long long bb[4] = {b0.x, b0.y, b1.x, b1.y};
            unsigned long long a2[4] = {splat2(a.x), splat2(a.y), splat2(a.z), splat2(a.w)};
            #pragma unroll
            for (int r = 0; r < 4; r++)
                #pragma unroll
                for (int p = 0; p < 4; p++)
                    acc[r][p] = ffma2(a2[r], bb[p], acc[r][p]);
        }

        float en[8];
        {
            float4 e0 = *reinterpret_cast<const float4*>(&g_en2[kc + 8 * cg]);
            float4 e1 = *reinterpret_cast<const float4*>(&g_en2[kc + 8 * cg + 4]);
            en[0] = e0.x; en[1] = e0.y; en[2] = e0.z; en[3] = e0.w;
            en[4] = e1.x; en[5] = e1.y; en[6] = e1.z; en[7] = e1.w;
        }
        #pragma unroll
        for (int r = 0; r < 4; r++) {
            #pragma unroll
            for (int p = 0; p < 4; p++) {
                float2 v = unpack2(acc[r][p]);
                int k0 = kc + 8 * cg + 2 * p;
                float s0 = en[2 * p + 0] - 2.f * v.x;
                float s1 = en[2 * p + 1] - 2.f * v.y;
                if (s0 < bestv[r]) { bestv[r] = s0; bestk[r] = k0; }
                if (s1 < bestv[r]) { bestv[r] = s1; bestk[r] = k0 + 1; }
            }
        }
    }

    // Cross-cg reduction (first-min tie-break preserved by ascending k order)
    __syncthreads();
    float* rv = sm;                          // [128][16]
    int*   ri = (int*)(sm + 128 * 16);       // [128][16]
    #pragma unroll
    for (int r = 0; r < 4; r++) {
        rv[(4 * rg + r) * 16 + cg] = bestv[r];
        ri[(4 * rg + r) * 16 + cg] = bestk[r];
    }
    __syncthreads();
    if (tid < 128) {
        float bv = rv[tid * 16];
        int   bk = ri[tid * 16];
        #pragma unroll
        for (int c = 1; c < 16; c++) {
            float v  = rv[tid * 16 + c];
            int   k2 = ri[tid * 16 + c];
            if (v < bv || (v == bv && k2 < bk)) { bv = v; bk = k2; }
        }
        g_idx[n0 + tid] = bk;
    }
}

// ---------------------------------------------------------------------------
// K2a: histogram counts
// ---------------------------------------------------------------------------
__global__ void k_count() {
    int n = blockIdx.x * 256 + threadIdx.x;
    atomicAdd(&g_cnt[g_idx[n]], 1);
}

// ---------------------------------------------------------------------------
// K2b: scatter-add (1-MU)*z into pre-initialized emb_sum_n output region.
// ---------------------------------------------------------------------------
__global__ void k_scatter(const float* __restrict__ z, float* __restrict__ out_sum) {
    int i = blockIdx.x * 256 + threadIdx.x;      // over Bz*Dd*Tt
    int t = i & 2047;
    int d = (i >> 11) & 127;
    int b = i >> 18;
    int k = g_idx[(b << 11) + t];
    atomicAdd(&out_sum[k * Dd + d], __fmul_rn(C1f, z[i]));
}

// ---------------------------------------------------------------------------
// K3: z_vq_out gather + z_enc_loss (double accumulate).
// ---------------------------------------------------------------------------
__global__ void k_output(const float* __restrict__ z, const float* __restrict__ emb,
                         float* __restrict__ out_zvq) {
    __shared__ int    kk[32];
    __shared__ float  er[32 * 133];
    __shared__ double red[256];
    int tx  = threadIdx.x;            // 32
    int ty  = threadIdx.y;            // 8
    int tid = ty * 32 + tx;
    int t0  = blockIdx.x * 32;
    int b   = blockIdx.y;

    if (tid < 32) kk[tid] = g_idx[b * Tt + t0 + tid];
    __syncthreads();
    for (int i = tid; i < 32 * 32; i += 256) {
        int r  = i >> 5;
        int d4 = (i & 31) << 2;
        float4 v = *reinterpret_cast<const float4*>(emb + (size_t)kk[r] * Dd + d4);
        er[r * 133 + d4 + 0] = v.x;
        er[r * 133 + d4 + 1] = v.y;
        er[r * 133 + d4 + 2] = v.z;
        er[r * 133 + d4 + 3] = v.w;
    }
    __syncthreads();

    double loc = 0.0;
    size_t base = (size_t)b * Dd * Tt + t0 + tx;
    for (int d = ty; d < Dd; d += 8) {
        float v  = er[tx * 133 + d];
        float zv = z[base + (size_t)d * Tt];
        out_zvq[base + (size_t)d * Tt] = v;
        float df = v - zv;
        loc += (double)df * (double)df;
    }
    red[tid] = loc;
    __syncthreads();
    for (int s = 128; s > 0; s >>= 1) {
        if (tid < s) red[tid] += red[tid + s];
        __syncthreads();
    }
    if (tid == 0) atomicAdd(&g_loss, red[0]);
}

// ---------------------------------------------------------------------------
// K4: emb_new, emb_elem_n, dk partials
// ---------------------------------------------------------------------------
__global__ void k_new(const float* __restrict__ emb, const float* __restrict__ emb_elem,
                      const float* __restrict__ emb_rand,
                      const float* __restrict__ out_sum,
                      float* __restrict__ out_new, float* __restrict__ out_elem) {
    __shared__ double red[256];
    int i = blockIdx.x * 256 + threadIdx.x;  // Kk*Dd
    int k = i >> 7;
    int d = i & 127;
    float ee = __fadd_rn(__fmul_rn(MUf, emb_elem[k]), __fmul_rn(C1f, (float)g_cnt[k]));
    float v  = (ee >= 1.0f) ? (out_sum[i] / ee) : emb_rand[i];
    out_new[i] = v;
    if (d == 0) out_elem[k] = ee;
    float df = v - emb[i];
    red[threadIdx.x] = (double)df * (double)df;
    __syncthreads();
    for (int s = 128; s > 0; s >>= 1) {
        if (threadIdx.x < s) red[threadIdx.x] += red[threadIdx.x + s];
        __syncthreads();
    }
    if (threadIdx.x == 0) atomicAdd(&g_dk2, red[0]);
}

// ---------------------------------------------------------------------------
// K5: entropy + scalar outputs
// ---------------------------------------------------------------------------
__global__ void k_final(float* __restrict__ out) {
    __shared__ double red[256];
    int tid = threadIdx.x;
    double s = 0.0;
    for (int k = tid; k < Kk; k += 256) {
        float p = (float)g_cnt[k] * (1.0f / 65536.0f);
        s += (double)(p * logf(p + 1e-8f));
    }
    red[tid] = s;
    __syncthreads();
    for (int st = 128; st > 0; st >>= 1) {
        if (tid < st) red[tid] += red[tid + st];
        __syncthreads();
    }
    if (tid == 0) {
        out[OFF_LOSS] = (float)g_loss;
        out[OFF_ENT]  = expf(-(float)red[0]);
        out[OFF_DK]   = (float)(sqrt(g_dk2) / 512.0);
    }
}

// ---------------------------------------------------------------------------
extern "C" void kernel_launch(void* const* d_in, const int* in_sizes, int n_in,
                              void* d_out, int out_size) {
    const float* z        = (const float*)d_in[0];
    const float* emb      = (const float*)d_in[1];
    const float* emb_sum  = (const float*)d_in[2];
    const float* emb_elem = (const float*)d_in[3];
    const float* emb_rand = (const float*)d_in[4];
    float* out      = (float*)d_out;
    float* out_zvq  = out + OFF_ZVQ;
    float* out_new  = out + OFF_EMBNEW;
    float* out_sum  = out + OFF_EMBSUM;
    float* out_elem = out + OFF_ELEM;

    const int assign_smem = (128 * 128 + 128 * 132) * (int)sizeof(float);  // 133120 B
    cudaFuncSetAttribute(k_assign, cudaFuncAttributeMaxDynamicSharedMemorySize, assign_smem);

    k_en2<<<Kk, 32>>>(emb);
    k_init<<<(Kk * Dd + 255) / 256, 256>>>(emb_sum, out_sum);
    k_assign<<<Nn / 128, AT, assign_smem>>>(z, emb);
    k_count<<<Nn / 256, 256>>>();
    k_scatter<<<(Bz * Dd * Tt) / 256, 256>>>(z, out_sum);
    k_output<<<dim3(Tt / 32, Bz), dim3(32, 8)>>>(z, emb, out_zvq);
    k_new<<<(Kk * Dd) / 256, 256>>>(emb, emb_elem, emb_rand, out_sum, out_new, out_elem);
    k_final<<<1, 256>>>(out);
}